// round 4
// baseline (speedup 1.0000x reference)
#include <cuda_runtime.h>

// Problem constants (fixed shapes from reference setup_inputs)
#define IMG_H   1536
#define IMG_W   1536
#define NR      191        // reference patches per axis: arange(0, 1528, 8)
#define PATCH   8
#define MAXC    31         // candidates per axis
#define WINDIM  38         // search window span
#define SW_DIM  1529       // valid 8x8-box positions per axis (1536-8+1)

#define WT_COLS 64         // window tile column stride (mult of 4 for LDS.128)
#define SWT_COLS 55        // Sc tile column stride

// Scratch: global 8x8 box-sum-of-squares map (and its row-pass intermediate)
__device__ float g_rowSq[IMG_H * SW_DIM];   // [x][y]: sum_q img[x][y+q]^2
__device__ float g_Sw[SW_DIM * SW_DIM];     // [x][y]: sum_{p,q} img[x+p][y+q]^2

// ---- packed f32x2 helpers (Blackwell; ptxas never auto-fuses FFMA2) ----
__device__ __forceinline__ unsigned long long pack2(float lo, float hi) {
    unsigned long long r;
    asm("mov.b64 %0, {%1, %2};" : "=l"(r) : "f"(lo), "f"(hi));
    return r;
}
__device__ __forceinline__ void unpack2(unsigned long long v, float& lo, float& hi) {
    asm("mov.b64 {%0, %1}, %2;" : "=f"(lo), "=f"(hi) : "l"(v));
}
__device__ __forceinline__ void ffma2(unsigned long long& d,
                                      unsigned long long a,
                                      unsigned long long b) {
    asm("fma.rn.f32x2 %0, %1, %2, %3;" : "=l"(d) : "l"(a), "l"(b), "l"(d));
}

// ---------------------------------------------------------------------------
// Pass 1: horizontal sliding sum of squares (8 wide)
// ---------------------------------------------------------------------------
__global__ void rowsq_kernel(const float* __restrict__ img) {
    int y = blockIdx.x * blockDim.x + threadIdx.x;
    int x = blockIdx.y;
    if (y >= SW_DIM) return;
    const float* row = img + x * IMG_W + y;
    float s = 0.f;
#pragma unroll
    for (int q = 0; q < PATCH; q++) { float v = row[q]; s += v * v; }
    g_rowSq[x * SW_DIM + y] = s;
}

// ---------------------------------------------------------------------------
// Pass 2: vertical sliding sum (8 tall) -> full 8x8 box sums of img^2
// ---------------------------------------------------------------------------
__global__ void boxsum_kernel() {
    int y = blockIdx.x * blockDim.x + threadIdx.x;
    int x = blockIdx.y;
    if (y >= SW_DIM) return;
    float s = 0.f;
#pragma unroll
    for (int p = 0; p < PATCH; p++) s += g_rowSq[(x + p) * SW_DIM + y];
    g_Sw[x * SW_DIM + y] = s;
}

// ---------------------------------------------------------------------------
// Main kernel: one CTA = 4 refs along y (shared window tile), 64 threads/ref,
// each thread computes a 4x4 candidate block via corr + precomputed box sums.
// Inner product evaluated with packed fma.rn.f32x2 over q-parity pairs.
// ---------------------------------------------------------------------------
__global__ void __launch_bounds__(256, 2)
pm_kernel(const float* __restrict__ img, float* __restrict__ out) {
    __shared__ __align__(16) float winS[WINDIM * WT_COLS];  // 38 x 64 floats
    __shared__ float swS[MAXC * SWT_COLS];                  // 31 x 55 floats

    const int ix  = blockIdx.y;          // ref x index
    const int iy0 = blockIdx.x * 4;      // first ref y index of this CTA
    const int rx  = ix * PATCH;          // ref patch top row
    const int cx0 = rx - 20;             // window tile origin row (may be <0)
    const int cy0 = iy0 * PATCH - 20;    // window tile origin col (may be <0)
    const int sx      = max(0, cx0);     // candidate x start (shared: same rx)
    const int sy_base = max(0, cy0);     // Sc tile origin col
    const int tid = threadIdx.x;

    // ---- cooperative load: window tile (zero-padded OOB) ----
    for (int e = tid; e < WINDIM * WT_COLS; e += 256) {
        int r = e >> 6;              // e / 64
        int c = e & 63;              // e % 64
        int gx = cx0 + r, gy = cy0 + c;
        float v = 0.f;
        if (gx >= 0 && gx < IMG_H && gy >= 0 && gy < IMG_W)
            v = img[gx * IMG_W + gy];
        winS[e] = v;
    }
    // ---- cooperative load: Sc tile (box-sum map), zero OOB ----
    for (int e = tid; e < MAXC * SWT_COLS; e += 256) {
        int r = e / SWT_COLS;
        int c = e - r * SWT_COLS;
        int gx = sx + r, gy = sy_base + c;
        float v = 0.f;
        if (gx < SW_DIM && gy < SW_DIM)
            v = g_Sw[gx * SW_DIM + gy];
        swS[e] = v;
    }
    __syncthreads();

    const int j  = tid >> 6;             // ref slot within CTA (0..3)
    const int t  = tid & 63;
    const int bu = t >> 3, bv = t & 7;   // 4x4 block coords in 8x8 block grid
    const int iy = iy0 + j;
    if (iy >= NR) return;                // partial last y-group (no more barriers)

    const int ry = iy * PATCH;
    // window-tile offsets
    const int xoff  = max(0, -cx0);                     // = max(0, 20 - rx)
    const int ywoff = max(20 - 8 * iy0, 8 * j);         // sy_j - cy0 (mult of 4)
    const int syoff = ywoff + cy0 - sy_base;            // sy_j - sy_base
    const int bcol  = 8 * j + 20;                       // base patch col in tile

    const int u0 = bu * 4, v0 = bv * 4;
    const int wrowbase = xoff + u0;
    const int wcolbase = ywoff + v0;                    // mult of 4 -> LDS.128 ok

    // ring of 4 base-patch rows, each as 4 packed (q even, q odd) pairs
    unsigned long long bp[4][4];
    // packed accumulators: [cu][v], lo = sum over even q, hi = sum over odd q
    unsigned long long accp[4][4];
#pragma unroll
    for (int cu = 0; cu < 4; cu++)
#pragma unroll
        for (int v = 0; v < 4; v++) accp[cu][v] = 0ULL;

    // ---- main correlation: 11 window rows, rolling base ring, f32x2 FMAs ----
#pragma unroll
    for (int tt = 0; tt < 11; tt++) {
        if (tt < 8) {
            // base row tt enters the ring at slot tt&3 (broadcast LDS: same
            // address for all lanes of a warp -> conflict-free)
            const float* brow = &winS[(20 + tt) * WT_COLS + bcol];
            float4 b0 = *reinterpret_cast<const float4*>(brow);
            float4 b1 = *reinterpret_cast<const float4*>(brow + 4);
            bp[tt & 3][0] = pack2(b0.x, b0.y);
            bp[tt & 3][1] = pack2(b0.z, b0.w);
            bp[tt & 3][2] = pack2(b1.x, b1.y);
            bp[tt & 3][3] = pack2(b1.z, b1.w);
        }
        // rows for masked (invalid) candidates may exceed tile: clamp (unused)
        int rr = wrowbase + tt;
        rr = rr < (WINDIM - 1) ? rr : (WINDIM - 1);
        const float* wrow = &winS[rr * WT_COLS + wcolbase];
        float4 wa = *reinterpret_cast<const float4*>(wrow);
        float4 wb = *reinterpret_cast<const float4*>(wrow + 4);
        float4 wc = *reinterpret_cast<const float4*>(wrow + 8);
        float w[12] = {wa.x, wa.y, wa.z, wa.w,
                       wb.x, wb.y, wb.z, wb.w,
                       wc.x, wc.y, wc.z, wc.w};
        unsigned long long wp[10];
#pragma unroll
        for (int k = 0; k < 10; k++) wp[k] = pack2(w[k], w[k + 1]);

#pragma unroll
        for (int cu = 0; cu < 4; cu++) {
            if (cu <= tt && tt - cu <= 7) {   // p = tt - cu in [0,7]
                const int p = tt - cu;
#pragma unroll
                for (int qh = 0; qh < 4; qh++) {   // q = 2*qh
#pragma unroll
                    for (int v = 0; v < 4; v++)
                        ffma2(accp[cu][v], bp[p & 3][qh], wp[2 * qh + v]);
                }
            }
        }
    }

    // ---- epilogue: d2 = Sb + Sc - 2*corr, sqrt, mask, store ----
    const int cntx = min(IMG_H, rx + 19) - PATCH - sx;
    const int sy_j = syoff + sy_base;
    const int cnty = min(IMG_W, ry + 19) - PATCH - sy_j;
    const float Sb = swS[min(rx, 20) * SWT_COLS + (ry - sy_base)];

    float* oref = out + (size_t)(ix * NR + iy) * (MAXC * MAXC);
#pragma unroll
    for (int cu = 0; cu < 4; cu++) {
        const int u = u0 + cu;
        if (u < MAXC) {
#pragma unroll
            for (int cv = 0; cv < 4; cv++) {
                const int v = v0 + cv;
                if (v < MAXC) {
                    float r = 0.f;
                    if (u < cntx && v < cnty) {
                        float lo, hi;
                        unpack2(accp[cu][cv], lo, hi);
                        float corr = lo + hi;
                        float Sc = swS[u * SWT_COLS + syoff + v];
                        float d2 = Sb + Sc - 2.f * corr;
                        r = sqrtf(fmaxf(d2, 0.f));
                    }
                    oref[u * MAXC + v] = r;
                }
            }
        }
    }
}

// ---------------------------------------------------------------------------
extern "C" void kernel_launch(void* const* d_in, const int* in_sizes, int n_in,
                              void* d_out, int out_size) {
    const float* img = (const float*)d_in[0];
    float* out = (float*)d_out;

    dim3 blk(256);
    dim3 g1((SW_DIM + 255) / 256, IMG_H);
    rowsq_kernel<<<g1, blk>>>(img);

    dim3 g2((SW_DIM + 255) / 256, SW_DIM);
    boxsum_kernel<<<g2, blk>>>();

    dim3 g3((NR + 3) / 4, NR);   // 48 x 191 CTAs
    pm_kernel<<<g3, blk>>>(img, out);
}

// round 6
// speedup vs baseline: 1.1787x; 1.1787x over previous
#include <cuda_runtime.h>

// Problem constants (fixed shapes from reference setup_inputs)
#define IMG_H   1536
#define IMG_W   1536
#define NR      191        // reference patches per axis: arange(0, 1528, 8)
#define PATCH   8
#define MAXC    31         // candidates per axis
#define WINDIM  38         // search window span

#define WT_COLS 64         // window tile column stride (mult of 4 for LDS.128)
#define RQ_COLS 56         // row-sq tile columns (used cols <= 54; reads winS col <= 62)
#define SW_COLS 56         // Sc tile column stride

// ---- packed f32x2 helpers (Blackwell; ptxas never auto-fuses FFMA2) ----
__device__ __forceinline__ unsigned long long pack2(float lo, float hi) {
    unsigned long long r;
    asm("mov.b64 %0, {%1, %2};" : "=l"(r) : "f"(lo), "f"(hi));
    return r;
}
__device__ __forceinline__ void unpack2(unsigned long long v, float& lo, float& hi) {
    asm("mov.b64 {%0, %1}, %2;" : "=f"(lo), "=f"(hi) : "l"(v));
}
__device__ __forceinline__ void ffma2(unsigned long long& d,
                                      unsigned long long a,
                                      unsigned long long b) {
    asm("fma.rn.f32x2 %0, %1, %2, %3;" : "=l"(d) : "l"(a), "l"(b), "l"(d));
}
__device__ __forceinline__ float sqrt_approx(float x) {
    float r;
    asm("sqrt.approx.f32 %0, %1;" : "=f"(r) : "f"(x));
    return r;
}
// streaming store: output is write-once, never re-read -> keep img in L2
__device__ __forceinline__ void store_cs(float* p, float v) {
    asm volatile("st.global.cs.f32 [%0], %1;" :: "l"(p), "f"(v) : "memory");
}

// ---------------------------------------------------------------------------
// Single fused kernel. One CTA = 4 refs along y sharing a 38x64 window tile.
// Stage A: load window tile.  Stage B: row sliding sum-of-squares (8 wide).
// Stage C: column sliding sum (8 tall) -> per-CTA Sc box-sum tile.
// Stage D: 64 threads/ref, each computes a 4x4 candidate block: packed-f32x2
//          correlation + d2 = Sb + Sc - 2*corr, sqrt, mask, store.
// ---------------------------------------------------------------------------
__global__ void __launch_bounds__(256, 2)
pm_kernel(const float* __restrict__ img, float* __restrict__ out) {
    __shared__ __align__(16) float winS[WINDIM * WT_COLS];  // 38 x 64 = 9728 B
    __shared__ float rqS[WINDIM * RQ_COLS];                 // 38 x 56 = 8512 B
    __shared__ float swS[MAXC * SW_COLS];                   // 31 x 56 = 6944 B

    const int ix  = blockIdx.y;          // ref x index
    const int iy0 = blockIdx.x * 4;      // first ref y index of this CTA
    const int rx  = ix * PATCH;          // ref patch top row
    const int cx0 = rx - 20;             // window tile origin row (may be <0)
    const int cy0 = iy0 * PATCH - 20;    // window tile origin col (may be <0)
    const int xoff = max(0, -cx0);       // tile row of candidate u=0
    const int tid = threadIdx.x;

    // ---- Stage A: cooperative load of window tile (zero-padded OOB) ----
    for (int e = tid; e < WINDIM * WT_COLS; e += 256) {
        int r = e >> 6;              // e / 64
        int c = e & 63;              // e % 64
        int gx = cx0 + r, gy = cy0 + c;
        float v = 0.f;
        if (gx >= 0 && gx < IMG_H && gy >= 0 && gy < IMG_W)
            v = img[gx * IMG_W + gy];
        winS[e] = v;
    }
    __syncthreads();

    // ---- Stage B: horizontal sliding sum of squares (8 wide) ----
    for (int e = tid; e < WINDIM * RQ_COLS; e += 256) {
        int r = e / RQ_COLS;
        int c = e - r * RQ_COLS;
        const float* p = &winS[r * WT_COLS + c];
        float s = 0.f;
#pragma unroll
        for (int q = 0; q < PATCH; q++) { float v = p[q]; s += v * v; }
        rqS[e] = s;
    }
    __syncthreads();

    // ---- Stage C: vertical sliding sum (8 tall) -> Sc tile ----
    // swS[u][c] = box-sum of img^2 at (sx+u, cy0+c); rows clamped for
    // masked (invalid) u near the top edge -> values unused.
    for (int e = tid; e < MAXC * SW_COLS; e += 256) {
        int u = e / SW_COLS;
        int c = e - u * SW_COLS;
        int r0 = xoff + u;
        float s = 0.f;
#pragma unroll
        for (int p = 0; p < PATCH; p++) {
            int rr = min(r0 + p, WINDIM - 1);
            s += rqS[rr * RQ_COLS + c];
        }
        swS[e] = s;
    }
    __syncthreads();

    // ---- Stage D ----
    const int j  = tid >> 6;             // ref slot within CTA (0..3)
    const int t  = tid & 63;
    const int bu = t >> 3, bv = t & 7;   // 4x4 block coords in 8x8 block grid
    const int iy = iy0 + j;
    if (iy >= NR) return;                // partial last y-group (no more barriers)

    const int ry = iy * PATCH;
    const int ywoff = max(20 - 8 * iy0, 8 * j);  // window start col in tile (mult of 4)
    const int bcol  = 8 * j + 20;                // base patch col in tile (even)

    const int u0 = bu * 4, v0 = bv * 4;
    const int wrowbase = xoff + u0;
    const int wcolbase = ywoff + v0;             // mult of 4 -> LDS.128 aligned

    // ring of 4 base-patch rows, each as 4 packed (q even, q odd) pairs,
    // loaded directly as aligned 8-byte broadcast LDS from the tile
    unsigned long long bp[4][4];
    // packed accumulators: [cu][v], lo = sum over even q, hi = sum over odd q
    unsigned long long accp[4][4];
#pragma unroll
    for (int cu = 0; cu < 4; cu++)
#pragma unroll
        for (int v = 0; v < 4; v++) accp[cu][v] = 0ULL;

#pragma unroll
    for (int tt = 0; tt < 11; tt++) {
        if (tt < 8) {
            const unsigned long long* brow =
                reinterpret_cast<const unsigned long long*>(
                    &winS[(20 + tt) * WT_COLS + bcol]);
            bp[tt & 3][0] = brow[0];
            bp[tt & 3][1] = brow[1];
            bp[tt & 3][2] = brow[2];
            bp[tt & 3][3] = brow[3];
        }
        // rows for masked (invalid) candidates may exceed tile: clamp (unused)
        int rr = min(wrowbase + tt, WINDIM - 1);
        const float* wrow = &winS[rr * WT_COLS + wcolbase];
        float4 wa = *reinterpret_cast<const float4*>(wrow);
        float4 wb = *reinterpret_cast<const float4*>(wrow + 4);
        float4 wc = *reinterpret_cast<const float4*>(wrow + 8);
        float w[12] = {wa.x, wa.y, wa.z, wa.w,
                       wb.x, wb.y, wb.z, wb.w,
                       wc.x, wc.y, wc.z, wc.w};

        // chunk by qh so only 4 packed window pairs are live at a time
#pragma unroll
        for (int qh = 0; qh < 4; qh++) {
            unsigned long long wp0 = pack2(w[2 * qh + 0], w[2 * qh + 1]);
            unsigned long long wp1 = pack2(w[2 * qh + 1], w[2 * qh + 2]);
            unsigned long long wp2 = pack2(w[2 * qh + 2], w[2 * qh + 3]);
            unsigned long long wp3 = pack2(w[2 * qh + 3], w[2 * qh + 4]);
#pragma unroll
            for (int cu = 0; cu < 4; cu++) {
                if (cu <= tt && tt - cu <= 7) {   // p = tt - cu in [0,7]
                    const int p = tt - cu;
                    ffma2(accp[cu][0], bp[p & 3][qh], wp0);
                    ffma2(accp[cu][1], bp[p & 3][qh], wp1);
                    ffma2(accp[cu][2], bp[p & 3][qh], wp2);
                    ffma2(accp[cu][3], bp[p & 3][qh], wp3);
                }
            }
        }
    }

    // ---- epilogue: d2 = Sb + Sc - 2*corr, sqrt, mask, store ----
    const int sx   = max(0, cx0);
    const int sy_j = max(0, ry - 20);
    const int cntx = min(IMG_H, rx + 19) - PATCH - sx;
    const int cnty = min(IMG_W, ry + 19) - PATCH - sy_j;
    const float Sb = swS[min(rx, 20) * SW_COLS + (8 * j + 20)];

    float* oref = out + (size_t)(ix * NR + iy) * (MAXC * MAXC);
#pragma unroll
    for (int cu = 0; cu < 4; cu++) {
        const int u = u0 + cu;
        if (u < MAXC) {
#pragma unroll
            for (int cv = 0; cv < 4; cv++) {
                const int v = v0 + cv;
                if (v < MAXC) {
                    float r = 0.f;
                    if (u < cntx && v < cnty) {
                        float lo, hi;
                        unpack2(accp[cu][cv], lo, hi);
                        float corr = lo + hi;
                        float Sc = swS[u * SW_COLS + ywoff + v];
                        float d2 = Sb + Sc - 2.f * corr;
                        r = sqrt_approx(fmaxf(d2, 0.f));
                    }
                    store_cs(&oref[u * MAXC + v], r);
                }
            }
        }
    }
}

// ---------------------------------------------------------------------------
extern "C" void kernel_launch(void* const* d_in, const int* in_sizes, int n_in,
                              void* d_out, int out_size) {
    const float* img = (const float*)d_in[0];
    float* out = (float*)d_out;

    dim3 blk(256);
    dim3 g((NR + 3) / 4, NR);   // 48 x 191 CTAs
    pm_kernel<<<g, blk>>>(img, out);
}

// round 7
// speedup vs baseline: 1.2014x; 1.0193x over previous
#include <cuda_runtime.h>

// Problem constants (fixed shapes from reference setup_inputs)
#define IMG_H   1536
#define IMG_W   1536
#define NR      191        // reference patches per axis: arange(0, 1528, 8)
#define PATCH   8
#define MAXC    31         // candidates per axis
#define WINDIM  38         // search window span

#define WT_COLS 64         // window tile column stride
#define RQ_COLS 56         // row-sq tile columns (used cols <= 54)
#define SW_COLS 56         // Sc tile column stride

typedef unsigned long long ull;

// ---- packed f32x2 helpers (Blackwell; ptxas never auto-fuses FFMA2) ----
__device__ __forceinline__ void unpack2(ull v, float& lo, float& hi) {
    asm("mov.b64 {%0, %1}, %2;" : "=f"(lo), "=f"(hi) : "l"(v));
}
__device__ __forceinline__ void ffma2(ull& d, ull a, ull b) {
    asm("fma.rn.f32x2 %0, %1, %2, %3;" : "=l"(d) : "l"(a), "l"(b), "l"(d));
}
__device__ __forceinline__ float sqrt_approx(float x) {
    float r;
    asm("sqrt.approx.f32 %0, %1;" : "=f"(r) : "f"(x));
    return r;
}
// streaming store: output is write-once, never re-read -> keep img in L2
__device__ __forceinline__ void store_cs(float* p, float v) {
    asm volatile("st.global.cs.f32 [%0], %1;" :: "l"(p), "f"(v) : "memory");
}

// ---------------------------------------------------------------------------
// Single fused kernel. One CTA = 4 refs along y sharing a 38x64 window tile.
// Stage A : load window tile.
// Stage B : row sliding sum-of-squares (8 wide) + build 1-float-shifted tile
//           copy (winS2) so ODD window pairs are 8B-aligned too.
// Stage C : column sliding sum (8 tall) -> per-CTA Sc box-sum tile.
// Stage D : 64 threads/ref, 4x4 candidate block each; pure-FFMA2 correlation
//           (all operand pairs are direct aligned 64-bit smem loads),
//           d2 = Sb + Sc - 2*corr, sqrt, mask, store.
// ---------------------------------------------------------------------------
__global__ void __launch_bounds__(256, 2)
pm_kernel(const float* __restrict__ img, float* __restrict__ out) {
    __shared__ __align__(16) float winS [WINDIM * WT_COLS];  // 38 x 64 = 9728 B
    __shared__ __align__(16) float winS2[WINDIM * WT_COLS];  // shifted by +1 col
    __shared__ float rqS[WINDIM * RQ_COLS];                  // 38 x 56 = 8512 B
    __shared__ float swS[MAXC * SW_COLS];                    // 31 x 56 = 6944 B

    const int ix  = blockIdx.y;          // ref x index
    const int iy0 = blockIdx.x * 4;      // first ref y index of this CTA
    const int rx  = ix * PATCH;          // ref patch top row
    const int cx0 = rx - 20;             // window tile origin row (may be <0)
    const int cy0 = iy0 * PATCH - 20;    // window tile origin col (may be <0)
    const int xoff = max(0, -cx0);       // tile row of candidate u=0
    const int tid = threadIdx.x;

    // ---- Stage A: cooperative load of window tile (zero-padded OOB) ----
    for (int e = tid; e < WINDIM * WT_COLS; e += 256) {
        int r = e >> 6;              // e / 64
        int c = e & 63;              // e % 64
        int gx = cx0 + r, gy = cy0 + c;
        float v = 0.f;
        if (gx >= 0 && gx < IMG_H && gy >= 0 && gy < IMG_W)
            v = img[gx * IMG_W + gy];
        winS[e] = v;
    }
    __syncthreads();

    // ---- Stage B: horizontal sliding sum of squares + shifted copy ----
    for (int e = tid; e < WINDIM * RQ_COLS; e += 256) {
        int r = e / RQ_COLS;
        int c = e - r * RQ_COLS;
        const float* p = &winS[r * WT_COLS + c];
        float s = 0.f;
#pragma unroll
        for (int q = 0; q < PATCH; q++) { float v = p[q]; s += v * v; }
        rqS[e] = s;
    }
    for (int e = tid; e < WINDIM * WT_COLS; e += 256) {
        int c = e & 63;
        winS2[e] = (c < 63) ? winS[e + 1] : 0.f;
    }
    __syncthreads();

    // ---- Stage C: vertical sliding sum (8 tall) -> Sc tile ----
    // swS[u][c] = box-sum of img^2 at (sx+u, cy0+c); rows clamped for
    // masked (invalid) u near the top edge -> values unused.
    for (int e = tid; e < MAXC * SW_COLS; e += 256) {
        int u = e / SW_COLS;
        int c = e - u * SW_COLS;
        int r0 = xoff + u;
        float s = 0.f;
#pragma unroll
        for (int p = 0; p < PATCH; p++) {
            int rr = min(r0 + p, WINDIM - 1);
            s += rqS[rr * RQ_COLS + c];
        }
        swS[e] = s;
    }
    __syncthreads();

    // ---- Stage D ----
    const int j  = tid >> 6;             // ref slot within CTA (0..3)
    const int t  = tid & 63;
    const int bu = t >> 3, bv = t & 7;   // 4x4 block coords in 8x8 block grid
    const int iy = iy0 + j;
    if (iy >= NR) return;                // partial last y-group (no more barriers)

    const int ry = iy * PATCH;
    const int ywoff = max(20 - 8 * iy0, 8 * j);  // window start col in tile (mult of 4)
    const int bcol  = 8 * j + 20;                // base patch col in tile (byte 16-aligned)

    const int u0 = bu * 4, v0 = bv * 4;
    const int wrowbase = xoff + u0;
    const int wcolbase = ywoff + v0;             // mult of 4 -> 16B aligned

    // ring of 4 base-patch rows, 4 packed (q even, q odd) pairs each,
    // loaded as aligned 16-byte broadcast LDS
    ull bp[4][4];
    // packed accumulators: [cu][v], lo = sum over even q, hi = sum over odd q
    ull accp[4][4];
#pragma unroll
    for (int cu = 0; cu < 4; cu++)
#pragma unroll
        for (int v = 0; v < 4; v++) accp[cu][v] = 0ULL;

#pragma unroll
    for (int tt = 0; tt < 11; tt++) {
        if (tt < 8) {
            const ulonglong2* brow = reinterpret_cast<const ulonglong2*>(
                &winS[(20 + tt) * WT_COLS + bcol]);
            ulonglong2 b0 = brow[0], b1 = brow[1];
            bp[tt & 3][0] = b0.x; bp[tt & 3][1] = b0.y;
            bp[tt & 3][2] = b1.x; bp[tt & 3][3] = b1.y;
        }
        // rows for masked (invalid) candidates may exceed tile: clamp (unused)
        int rr = min(wrowbase + tt, WINDIM - 1);
        // all 10 window pairs as ALIGNED 64-bit loads (no pack movs):
        // even-k pairs from winS, odd-k pairs from the shifted winS2
        const float* weRow = &winS [rr * WT_COLS + wcolbase];
        const float* woRow = &winS2[rr * WT_COLS + wcolbase];
        ulonglong2 e01 = *reinterpret_cast<const ulonglong2*>(weRow);      // k=0,2
        ulonglong2 o01 = *reinterpret_cast<const ulonglong2*>(woRow);      // k=1,3
        ulonglong2 e23 = *reinterpret_cast<const ulonglong2*>(weRow + 4);  // k=4,6
        ulonglong2 o23 = *reinterpret_cast<const ulonglong2*>(woRow + 4);  // k=5,7
        ull e4 = *reinterpret_cast<const ull*>(weRow + 8);                 // k=8
        ull o4 = *reinterpret_cast<const ull*>(woRow + 8);                 // k=9
        ull wp[10] = {e01.x, o01.x, e01.y, o01.y,
                      e23.x, o23.x, e23.y, o23.y, e4, o4};

#pragma unroll
        for (int cu = 0; cu < 4; cu++) {
            if (cu <= tt && tt - cu <= 7) {   // p = tt - cu in [0,7]
                const int p = (tt - cu) & 3;
#pragma unroll
                for (int qh = 0; qh < 4; qh++) {
                    ffma2(accp[cu][0], bp[p][qh], wp[2 * qh + 0]);
                    ffma2(accp[cu][1], bp[p][qh], wp[2 * qh + 1]);
                    ffma2(accp[cu][2], bp[p][qh], wp[2 * qh + 2]);
                    ffma2(accp[cu][3], bp[p][qh], wp[2 * qh + 3]);
                }
            }
        }
    }

    // ---- epilogue: d2 = Sb + Sc - 2*corr, sqrt, mask, store ----
    const int sx   = max(0, cx0);
    const int sy_j = max(0, ry - 20);
    const int cntx = min(IMG_H, rx + 19) - PATCH - sx;
    const int cnty = min(IMG_W, ry + 19) - PATCH - sy_j;
    const float Sb = swS[min(rx, 20) * SW_COLS + (8 * j + 20)];

    float* oref = out + (size_t)(ix * NR + iy) * (MAXC * MAXC);
#pragma unroll
    for (int cu = 0; cu < 4; cu++) {
        const int u = u0 + cu;
        if (u < MAXC) {
#pragma unroll
            for (int cv = 0; cv < 4; cv++) {
                const int v = v0 + cv;
                if (v < MAXC) {
                    float r = 0.f;
                    if (u < cntx && v < cnty) {
                        float lo, hi;
                        unpack2(accp[cu][cv], lo, hi);
                        float corr = lo + hi;
                        float Sc = swS[u * SW_COLS + ywoff + v];
                        float d2 = Sb + Sc - 2.f * corr;
                        r = sqrt_approx(fmaxf(d2, 0.f));
                    }
                    store_cs(&oref[u * MAXC + v], r);
                }
            }
        }
    }
}

// ---------------------------------------------------------------------------
extern "C" void kernel_launch(void* const* d_in, const int* in_sizes, int n_in,
                              void* d_out, int out_size) {
    const float* img = (const float*)d_in[0];
    float* out = (float*)d_out;

    dim3 blk(256);
    dim3 g((NR + 3) / 4, NR);   // 48 x 191 CTAs
    pm_kernel<<<g, blk>>>(img, out);
}

// round 14
// speedup vs baseline: 1.2108x; 1.0078x over previous
#include <cuda_runtime.h>

// Problem constants (fixed shapes from reference setup_inputs)
#define IMG_H   1536
#define IMG_W   1536
#define NR      191        // reference patches per axis: arange(0, 1528, 8)
#define PATCH   8
#define MAXC    31         // candidates per axis
#define WINDIM  38         // search window span

#define WT_COLS 64         // window tile column stride
#define RQ_COLS 56         // row-sq tile columns (used cols <= 54)
#define SW_COLS 56         // Sc tile column stride

typedef unsigned long long ull;

// ---- packed f32x2 helpers (Blackwell; ptxas never auto-fuses FFMA2) ----
__device__ __forceinline__ void unpack2(ull v, float& lo, float& hi) {
    asm("mov.b64 {%0, %1}, %2;" : "=f"(lo), "=f"(hi) : "l"(v));
}
__device__ __forceinline__ void ffma2(ull& d, ull a, ull b) {
    asm("fma.rn.f32x2 %0, %1, %2, %3;" : "=l"(d) : "l"(a), "l"(b), "l"(d));
}
__device__ __forceinline__ float sqrt_approx(float x) {
    float r;
    asm("sqrt.approx.f32 %0, %1;" : "=f"(r) : "f"(x));
    return r;
}
// streaming store: output is write-once, never re-read -> keep img in L2
__device__ __forceinline__ void store_cs(float* p, float v) {
    asm volatile("st.global.cs.f32 [%0], %1;" :: "l"(p), "f"(v) : "memory");
}

// ---------------------------------------------------------------------------
// Single fused kernel (R7 structure — proven on HW at 264us). One CTA = 4
// refs along y sharing a 38x64 window tile.
// Stage A : load window tile (scalar, zero-padded OOB).
// Stage B : row sliding sum-of-squares (8 wide) + 1-float-shifted tile copy
//           (winS2) so ODD window pairs are 8B-aligned.
// Stage C : column sliding sum (8 tall) -> per-CTA Sc box-sum tile.
// Stage D : 64 threads/ref, 4x4 candidate block; pure-FFMA2 correlation.
//           NEW vs R7: window-row loads are software-pipelined one row ahead
//           (wp/wn rotate, renamed away by full unroll) and the cu loop runs
//           descending so freshly-loaded base rows are consumed last.
// ---------------------------------------------------------------------------
__global__ void __launch_bounds__(256, 2)
pm_kernel(const float* __restrict__ img, float* __restrict__ out) {
    __shared__ __align__(16) float winS [WINDIM * WT_COLS];  // 38 x 64 = 9728 B
    __shared__ __align__(16) float winS2[WINDIM * WT_COLS];  // shifted by +1 col
    __shared__ float rqS[WINDIM * RQ_COLS];                  // 38 x 56 = 8512 B
    __shared__ float swS[MAXC * SW_COLS];                    // 31 x 56 = 6944 B

    const int ix  = blockIdx.y;          // ref x index
    const int iy0 = blockIdx.x * 4;      // first ref y index of this CTA
    const int rx  = ix * PATCH;          // ref patch top row
    const int cx0 = rx - 20;             // window tile origin row (may be <0)
    const int cy0 = iy0 * PATCH - 20;    // window tile origin col (may be <0)
    const int xoff = max(0, -cx0);       // tile row of candidate u=0
    const int tid = threadIdx.x;

    // ---- Stage A: cooperative load of window tile (zero-padded OOB) ----
    for (int e = tid; e < WINDIM * WT_COLS; e += 256) {
        int r = e >> 6;
        int c = e & 63;
        int gx = cx0 + r, gy = cy0 + c;
        float v = 0.f;
        if (gx >= 0 && gx < IMG_H && gy >= 0 && gy < IMG_W)
            v = img[gx * IMG_W + gy];
        winS[e] = v;
    }
    __syncthreads();

    // ---- Stage B: horizontal sliding sum of squares + shifted copy ----
    for (int e = tid; e < WINDIM * RQ_COLS; e += 256) {
        int r = e / RQ_COLS;
        int c = e - r * RQ_COLS;
        const float* p = &winS[r * WT_COLS + c];
        float s = 0.f;
#pragma unroll
        for (int q = 0; q < PATCH; q++) { float v = p[q]; s += v * v; }
        rqS[e] = s;
    }
    for (int e = tid; e < WINDIM * WT_COLS; e += 256) {
        int c = e & 63;
        winS2[e] = (c < 63) ? winS[e + 1] : 0.f;
    }
    __syncthreads();

    // ---- Stage C: vertical sliding sum (8 tall) -> Sc tile ----
    // swS[u][c] = box-sum of img^2 at (sx+u, cy0+c); rows clamped for
    // masked (invalid) u near the top edge -> values unused.
    for (int e = tid; e < MAXC * SW_COLS; e += 256) {
        int u = e / SW_COLS;
        int c = e - u * SW_COLS;
        int r0 = xoff + u;
        float s = 0.f;
#pragma unroll
        for (int p = 0; p < PATCH; p++) {
            int rr = min(r0 + p, WINDIM - 1);
            s += rqS[rr * RQ_COLS + c];
        }
        swS[e] = s;
    }
    __syncthreads();

    // ---- Stage D ----
    const int j  = tid >> 6;             // ref slot within CTA (0..3)
    const int t  = tid & 63;
    const int bu = t >> 3, bv = t & 7;   // 4x4 block coords in 8x8 block grid
    const int iy = iy0 + j;
    if (iy >= NR) return;                // partial last y-group (no more barriers)

    const int ry = iy * PATCH;
    const int ywoff = max(20 - 8 * iy0, 8 * j);  // window start col in tile (mult of 4)
    const int bcol  = 8 * j + 20;                // base patch col in tile (16B-aligned)

    const int u0 = bu * 4, v0 = bv * 4;
    const int wrowbase = xoff + u0;
    const int wcolbase = ywoff + v0;             // mult of 4 -> 16B aligned

    // ring of 4 base-patch rows, 4 packed (q even, q odd) pairs each
    ull bp[4][4];
    // packed accumulators: [cu][v], lo = sum over even q, hi = sum over odd q
    ull accp[4][4];
#pragma unroll
    for (int cu = 0; cu < 4; cu++)
#pragma unroll
        for (int v = 0; v < 4; v++) accp[cu][v] = 0ULL;

    // ---- prologue: window pairs for row tt=0 ----
    ull wp[10];
    {
        int rr = min(wrowbase, WINDIM - 1);
        const float* we = &winS [rr * WT_COLS + wcolbase];
        const float* wo = &winS2[rr * WT_COLS + wcolbase];
        ulonglong2 e01 = *reinterpret_cast<const ulonglong2*>(we);
        ulonglong2 o01 = *reinterpret_cast<const ulonglong2*>(wo);
        ulonglong2 e23 = *reinterpret_cast<const ulonglong2*>(we + 4);
        ulonglong2 o23 = *reinterpret_cast<const ulonglong2*>(wo + 4);
        wp[0] = e01.x; wp[1] = o01.x; wp[2] = e01.y; wp[3] = o01.y;
        wp[4] = e23.x; wp[5] = o23.x; wp[6] = e23.y; wp[7] = o23.y;
        wp[8] = *reinterpret_cast<const ull*>(we + 8);
        wp[9] = *reinterpret_cast<const ull*>(wo + 8);
    }

#pragma unroll
    for (int tt = 0; tt < 11; tt++) {
        // base row tt enters the ring (broadcast LDS; consumed LAST below)
        if (tt < 8) {
            const ulonglong2* brow = reinterpret_cast<const ulonglong2*>(
                &winS[(20 + tt) * WT_COLS + bcol]);
            ulonglong2 b0 = brow[0], b1 = brow[1];
            bp[tt & 3][0] = b0.x; bp[tt & 3][1] = b0.y;
            bp[tt & 3][2] = b1.x; bp[tt & 3][3] = b1.y;
        }
        // prefetch window pairs for row tt+1 (hidden behind this row's FMAs)
        ull wn[10];
        if (tt + 1 < 11) {
            int rr = min(wrowbase + tt + 1, WINDIM - 1);  // clamped rows = masked
            const float* we = &winS [rr * WT_COLS + wcolbase];
            const float* wo = &winS2[rr * WT_COLS + wcolbase];
            ulonglong2 e01 = *reinterpret_cast<const ulonglong2*>(we);
            ulonglong2 o01 = *reinterpret_cast<const ulonglong2*>(wo);
            ulonglong2 e23 = *reinterpret_cast<const ulonglong2*>(we + 4);
            ulonglong2 o23 = *reinterpret_cast<const ulonglong2*>(wo + 4);
            wn[0] = e01.x; wn[1] = o01.x; wn[2] = e01.y; wn[3] = o01.y;
            wn[4] = e23.x; wn[5] = o23.x; wn[6] = e23.y; wn[7] = o23.y;
            wn[8] = *reinterpret_cast<const ull*>(we + 8);
            wn[9] = *reinterpret_cast<const ull*>(wo + 8);
        }

        // FMAs for row tt, cu DESCENDING: oldest base rows first, so the
        // bp row loaded this iteration (cu=0, p=tt) is consumed last.
#pragma unroll
        for (int cu = 3; cu >= 0; cu--) {
            if (cu <= tt && tt - cu <= 7) {   // p = tt - cu in [0,7]
                const int p = (tt - cu) & 3;
#pragma unroll
                for (int qh = 0; qh < 4; qh++) {
                    ffma2(accp[cu][0], bp[p][qh], wp[2 * qh + 0]);
                    ffma2(accp[cu][1], bp[p][qh], wp[2 * qh + 1]);
                    ffma2(accp[cu][2], bp[p][qh], wp[2 * qh + 2]);
                    ffma2(accp[cu][3], bp[p][qh], wp[2 * qh + 3]);
                }
            }
        }

        // rotate (full unroll -> register renaming, no movs)
        if (tt + 1 < 11) {
#pragma unroll
            for (int k = 0; k < 10; k++) wp[k] = wn[k];
        }
    }

    // ---- epilogue: d2 = Sb + Sc - 2*corr, sqrt, mask, store ----
    const int sx   = max(0, cx0);
    const int sy_j = max(0, ry - 20);
    const int cntx = min(IMG_H, rx + 19) - PATCH - sx;
    const int cnty = min(IMG_W, ry + 19) - PATCH - sy_j;
    const float Sb = swS[min(rx, 20) * SW_COLS + (8 * j + 20)];

    float* oref = out + (size_t)(ix * NR + iy) * (MAXC * MAXC);
#pragma unroll
    for (int cu = 0; cu < 4; cu++) {
        const int u = u0 + cu;
        if (u < MAXC) {
#pragma unroll
            for (int cv = 0; cv < 4; cv++) {
                const int v = v0 + cv;
                if (v < MAXC) {
                    float r = 0.f;
                    if (u < cntx && v < cnty) {
                        float lo, hi;
                        unpack2(accp[cu][cv], lo, hi);
                        float corr = lo + hi;
                        float Sc = swS[u * SW_COLS + ywoff + v];
                        float d2 = Sb + Sc - 2.f * corr;
                        r = sqrt_approx(fmaxf(d2, 0.f));
                    }
                    store_cs(&oref[u * MAXC + v], r);
                }
            }
        }
    }
}

// ---------------------------------------------------------------------------
extern "C" void kernel_launch(void* const* d_in, const int* in_sizes, int n_in,
                              void* d_out, int out_size) {
    const float* img = (const float*)d_in[0];
    float* out = (float*)d_out;

    dim3 blk(256);
    dim3 g((NR + 3) / 4, NR);   // 48 x 191 CTAs
    pm_kernel<<<g, blk>>>(img, out);
}

// round 15
// speedup vs baseline: 1.3578x; 1.1214x over previous
#include <cuda_runtime.h>

// Problem constants (fixed shapes from reference setup_inputs)
#define IMG_H   1536
#define IMG_W   1536
#define NR      191        // reference patches per axis: arange(0, 1528, 8)
#define PATCH   8
#define MAXC    31         // candidates per axis
#define WINDIM  38         // search window span
#define KX      4          // x-tiles marched per CTA

#define WT_COLS 64         // window tile column stride
#define RQ_COLS 56         // row-sq tile columns (used cols <= 54)
#define SW_COLS 56         // Sc tile column stride
#define TILE_E  (WINDIM * WT_COLS)   // 2432 floats

typedef unsigned long long ull;

// ---- packed f32x2 helpers (Blackwell; ptxas never auto-fuses FFMA2) ----
__device__ __forceinline__ void unpack2(ull v, float& lo, float& hi) {
    asm("mov.b64 {%0, %1}, %2;" : "=f"(lo), "=f"(hi) : "l"(v));
}
__device__ __forceinline__ void ffma2(ull& d, ull a, ull b) {
    asm("fma.rn.f32x2 %0, %1, %2, %3;" : "=l"(d) : "l"(a), "l"(b), "l"(d));
}
__device__ __forceinline__ float sqrt_approx(float x) {
    float r;
    asm("sqrt.approx.f32 %0, %1;" : "=f"(r) : "f"(x));
    return r;
}
// streaming store: output is write-once, never re-read -> keep img in L2
__device__ __forceinline__ void store_cs(float* p, float v) {
    asm volatile("st.global.cs.f32 [%0], %1;" :: "l"(p), "f"(v) : "memory");
}

// ---------------------------------------------------------------------------
// Fused kernel with per-CTA x-march. One CTA = 4 refs along y x KX refs
// along x. y-side geometry (columns) is invariant across the march, so the
// window tile for step k+1 is prefetched into REGISTERS while step k's
// B/C/D stages run, then committed to smem after a barrier — hiding the
// Stage-A global latency for all but the first step.
// Stages B/C/D are the R14 HW-proven bodies verbatim (D's early-return is
// converted to predication because barriers now follow it).
// ---------------------------------------------------------------------------
__global__ void __launch_bounds__(256, 2)
pm_kernel(const float* __restrict__ img, float* __restrict__ out) {
    __shared__ __align__(16) float winS [TILE_E];            // 9728 B
    __shared__ __align__(16) float winS2[TILE_E];            // shifted +1 col
    __shared__ float rqS[WINDIM * RQ_COLS];                  // 8512 B
    __shared__ float swS[MAXC * SW_COLS];                    // 6944 B

    const int tid = threadIdx.x;
    const int iy0 = blockIdx.x * 4;          // first ref y index of this CTA
    const int ix0 = blockIdx.y * KX;         // first ref x index of this CTA
    const int cnt = min(KX, NR - ix0);       // x-steps this CTA performs
    const int cy0 = iy0 * PATCH - 20;        // window tile origin col (const)

    // ---- y-side constants for Stage D (invariant across the march) ----
    const int j  = tid >> 6;                 // ref slot within CTA (0..3)
    const int t  = tid & 63;
    const int bu = t >> 3, bv = t & 7;
    const int iy = iy0 + j;
    const int ry = iy * PATCH;
    const int ywoff = max(20 - 8 * iy0, 8 * j);
    const int bcol  = 8 * j + 20;            // 16B-aligned
    const int u0 = bu * 4, v0 = bv * 4;
    const int wcolbase = ywoff + v0;         // mult of 4 -> 16B aligned
    const int sy_j = max(0, ry - 20);
    const int cnty = min(IMG_W, ry + 19) - PATCH - sy_j;

    // ---- prologue: load tile k=0 (scalar, zero-padded OOB) ----
    {
        const int cx0p = ix0 * PATCH - 20;
        for (int e = tid; e < TILE_E; e += 256) {
            int r = e >> 6;
            int c = e & 63;
            int gx = cx0p + r, gy = cy0 + c;
            float v = 0.f;
            if (gx >= 0 && gx < IMG_H && gy >= 0 && gy < IMG_W)
                v = img[gx * IMG_W + gy];
            winS[e] = v;
        }
    }
    __syncthreads();

    for (int k = 0; k < cnt; k++) {
        const int rx   = (ix0 + k) * PATCH;  // ref patch top row, this step
        const int cx0  = rx - 20;
        const int xoff = max(0, -cx0);

        // ---- prefetch tile k+1 into registers (rows shift by +8) ----
        float pf[10];
        const bool havepf = (k + 1 < cnt);
        if (havepf) {
            const int cx0n = cx0 + PATCH;
#pragma unroll
            for (int s = 0; s < 10; s++) {
                int e = tid + s * 256;
                float v = 0.f;
                if (e < TILE_E) {
                    int r = e >> 6;
                    int c = e & 63;
                    int gx = cx0n + r, gy = cy0 + c;
                    if (gx >= 0 && gx < IMG_H && gy >= 0 && gy < IMG_W)
                        v = img[gx * IMG_W + gy];
                }
                pf[s] = v;
            }
        }

        // ---- Stage B: horizontal sliding sum of squares + shifted copy ----
        for (int e = tid; e < WINDIM * RQ_COLS; e += 256) {
            int r = e / RQ_COLS;
            int c = e - r * RQ_COLS;
            const float* p = &winS[r * WT_COLS + c];
            float s = 0.f;
#pragma unroll
            for (int q = 0; q < PATCH; q++) { float v = p[q]; s += v * v; }
            rqS[e] = s;
        }
        for (int e = tid; e < TILE_E; e += 256) {
            int c = e & 63;
            winS2[e] = (c < 63) ? winS[e + 1] : 0.f;
        }
        __syncthreads();

        // ---- Stage C: vertical sliding sum (8 tall) -> Sc tile ----
        // rows clamped for masked (invalid) u near the top edge -> unused
        for (int e = tid; e < MAXC * SW_COLS; e += 256) {
            int u = e / SW_COLS;
            int c = e - u * SW_COLS;
            int r0 = xoff + u;
            float s = 0.f;
#pragma unroll
            for (int p = 0; p < PATCH; p++) {
                int rr = min(r0 + p, WINDIM - 1);
                s += rqS[rr * RQ_COLS + c];
            }
            swS[e] = s;
        }
        __syncthreads();

        // ---- Stage D (predicated; NO barriers inside) ----
        if (iy < NR) {
            const int wrowbase = xoff + u0;

            ull bp[4][4];
            ull accp[4][4];
#pragma unroll
            for (int cu = 0; cu < 4; cu++)
#pragma unroll
                for (int v = 0; v < 4; v++) accp[cu][v] = 0ULL;

            // prologue: window pairs for row tt=0
            ull wp[10];
            {
                int rr = min(wrowbase, WINDIM - 1);
                const float* we = &winS [rr * WT_COLS + wcolbase];
                const float* wo = &winS2[rr * WT_COLS + wcolbase];
                ulonglong2 e01 = *reinterpret_cast<const ulonglong2*>(we);
                ulonglong2 o01 = *reinterpret_cast<const ulonglong2*>(wo);
                ulonglong2 e23 = *reinterpret_cast<const ulonglong2*>(we + 4);
                ulonglong2 o23 = *reinterpret_cast<const ulonglong2*>(wo + 4);
                wp[0] = e01.x; wp[1] = o01.x; wp[2] = e01.y; wp[3] = o01.y;
                wp[4] = e23.x; wp[5] = o23.x; wp[6] = e23.y; wp[7] = o23.y;
                wp[8] = *reinterpret_cast<const ull*>(we + 8);
                wp[9] = *reinterpret_cast<const ull*>(wo + 8);
            }

#pragma unroll
            for (int tt = 0; tt < 11; tt++) {
                if (tt < 8) {
                    const ulonglong2* brow = reinterpret_cast<const ulonglong2*>(
                        &winS[(20 + tt) * WT_COLS + bcol]);
                    ulonglong2 b0 = brow[0], b1 = brow[1];
                    bp[tt & 3][0] = b0.x; bp[tt & 3][1] = b0.y;
                    bp[tt & 3][2] = b1.x; bp[tt & 3][3] = b1.y;
                }
                ull wn[10];
                if (tt + 1 < 11) {
                    int rr = min(wrowbase + tt + 1, WINDIM - 1);
                    const float* we = &winS [rr * WT_COLS + wcolbase];
                    const float* wo = &winS2[rr * WT_COLS + wcolbase];
                    ulonglong2 e01 = *reinterpret_cast<const ulonglong2*>(we);
                    ulonglong2 o01 = *reinterpret_cast<const ulonglong2*>(wo);
                    ulonglong2 e23 = *reinterpret_cast<const ulonglong2*>(we + 4);
                    ulonglong2 o23 = *reinterpret_cast<const ulonglong2*>(wo + 4);
                    wn[0] = e01.x; wn[1] = o01.x; wn[2] = e01.y; wn[3] = o01.y;
                    wn[4] = e23.x; wn[5] = o23.x; wn[6] = e23.y; wn[7] = o23.y;
                    wn[8] = *reinterpret_cast<const ull*>(we + 8);
                    wn[9] = *reinterpret_cast<const ull*>(wo + 8);
                }

#pragma unroll
                for (int cu = 3; cu >= 0; cu--) {
                    if (cu <= tt && tt - cu <= 7) {   // p = tt - cu in [0,7]
                        const int p = (tt - cu) & 3;
#pragma unroll
                        for (int qh = 0; qh < 4; qh++) {
                            ffma2(accp[cu][0], bp[p][qh], wp[2 * qh + 0]);
                            ffma2(accp[cu][1], bp[p][qh], wp[2 * qh + 1]);
                            ffma2(accp[cu][2], bp[p][qh], wp[2 * qh + 2]);
                            ffma2(accp[cu][3], bp[p][qh], wp[2 * qh + 3]);
                        }
                    }
                }
                if (tt + 1 < 11) {
#pragma unroll
                    for (int kk = 0; kk < 10; kk++) wp[kk] = wn[kk];
                }
            }

            // ---- epilogue: d2 = Sb + Sc - 2*corr, sqrt, mask, store ----
            const int sx   = max(0, cx0);
            const int cntx = min(IMG_H, rx + 19) - PATCH - sx;
            const float Sb = swS[min(rx, 20) * SW_COLS + (8 * j + 20)];

            float* oref = out + (size_t)((ix0 + k) * NR + iy) * (MAXC * MAXC);
#pragma unroll
            for (int cu = 0; cu < 4; cu++) {
                const int u = u0 + cu;
                if (u < MAXC) {
#pragma unroll
                    for (int cv = 0; cv < 4; cv++) {
                        const int v = v0 + cv;
                        if (v < MAXC) {
                            float r = 0.f;
                            if (u < cntx && v < cnty) {
                                float lo, hi;
                                unpack2(accp[cu][cv], lo, hi);
                                float corr = lo + hi;
                                float Sc = swS[u * SW_COLS + ywoff + v];
                                float d2 = Sb + Sc - 2.f * corr;
                                r = sqrt_approx(fmaxf(d2, 0.f));
                            }
                            store_cs(&oref[u * MAXC + v], r);
                        }
                    }
                }
            }
        }
        __syncthreads();   // all reads of winS/winS2/swS for step k complete

        // ---- commit prefetched tile k+1 to smem ----
        if (havepf) {
#pragma unroll
            for (int s = 0; s < 10; s++) {
                int e = tid + s * 256;
                if (e < TILE_E) winS[e] = pf[s];
            }
        }
        __syncthreads();   // winS now holds tile k+1
    }
}

// ---------------------------------------------------------------------------
extern "C" void kernel_launch(void* const* d_in, const int* in_sizes, int n_in,
                              void* d_out, int out_size) {
    const float* img = (const float*)d_in[0];
    float* out = (float*)d_out;

    dim3 blk(256);
    dim3 g((NR + 3) / 4, (NR + KX - 1) / KX);   // 48 x 48 CTAs
    pm_kernel<<<g, blk>>>(img, out);
}

// round 16
// speedup vs baseline: 1.4219x; 1.0472x over previous
#include <cuda_runtime.h>

// Problem constants (fixed shapes from reference setup_inputs)
#define IMG_H   1536
#define IMG_W   1536
#define NR      191        // reference patches per axis: arange(0, 1528, 8)
#define PATCH   8
#define MAXC    31         // candidates per axis
#define WINDIM  38         // search window span
#define KX      8          // x-tiles marched per CTA

#define WT_COLS 64         // window tile column stride
#define RQ_COLS 56         // row-sq tile columns (used cols <= 54)
#define RQ_ROWS (8 * (KX - 1) + WINDIM)   // 94-row persistent ring
#define SW_COLS 56         // Sc tile column stride
#define TILE_E  (WINDIM * WT_COLS)        // 2432 floats

typedef unsigned long long ull;

// ---- packed f32x2 helpers (Blackwell; ptxas never auto-fuses FFMA2) ----
__device__ __forceinline__ void unpack2(ull v, float& lo, float& hi) {
    asm("mov.b64 {%0, %1}, %2;" : "=f"(lo), "=f"(hi) : "l"(v));
}
__device__ __forceinline__ void ffma2(ull& d, ull a, ull b) {
    asm("fma.rn.f32x2 %0, %1, %2, %3;" : "=l"(d) : "l"(a), "l"(b), "l"(d));
}
__device__ __forceinline__ float sqrt_approx(float x) {
    float r;
    asm("sqrt.approx.f32 %0, %1;" : "=f"(r) : "f"(x));
    return r;
}
// streaming store: output is write-once, never re-read -> keep img in L2
__device__ __forceinline__ void store_cs(float* p, float v) {
    asm volatile("st.global.cs.f32 [%0], %1;" :: "l"(p), "f"(v) : "memory");
}

// ---------------------------------------------------------------------------
// Fused kernel, per-CTA x-march of KX=8 tiles. One CTA = 4 refs along y x
// KX refs along x. NEW vs R15:
//  - rqS (row sum-of-squares) is a PERSISTENT 94-row ring across the march:
//    ring row base+r (base=8k) holds the map for image row ix0*8-20+8k+r,
//    which is march-invariant -> steps k>=1 compute only the 8 new rows.
//  - KX doubled 4->8 (halves prologue-A amortized cost).
// Everything else (prefetch-register tile commit, Stage B/C/D bodies,
// barrier structure) is R15 verbatim.
// ---------------------------------------------------------------------------
__global__ void __launch_bounds__(256, 2)
pm_kernel(const float* __restrict__ img, float* __restrict__ out) {
    __shared__ __align__(16) float winS [TILE_E];            // 9728 B
    __shared__ __align__(16) float winS2[TILE_E];            // shifted +1 col
    __shared__ __align__(16) float rqS[RQ_ROWS * RQ_COLS];   // 21056 B ring
    __shared__ float swS[MAXC * SW_COLS];                    // 6944 B
    // total static smem = 47456 B (< 48 KB cap); 94.9 KB/SM at 2 CTAs

    const int tid = threadIdx.x;
    const int iy0 = blockIdx.x * 4;          // first ref y index of this CTA
    const int ix0 = blockIdx.y * KX;         // first ref x index of this CTA
    const int cnt = min(KX, NR - ix0);       // x-steps this CTA performs
    const int cy0 = iy0 * PATCH - 20;        // window tile origin col (const)

    // ---- y-side constants for Stage D (invariant across the march) ----
    const int j  = tid >> 6;                 // ref slot within CTA (0..3)
    const int t  = tid & 63;
    const int bu = t >> 3, bv = t & 7;
    const int iy = iy0 + j;
    const int ry = iy * PATCH;
    const int ywoff = max(20 - 8 * iy0, 8 * j);
    const int bcol  = 8 * j + 20;            // 16B-aligned
    const int u0 = bu * 4, v0 = bv * 4;
    const int wcolbase = ywoff + v0;         // mult of 4 -> 16B aligned
    const int sy_j = max(0, ry - 20);
    const int cnty = min(IMG_W, ry + 19) - PATCH - sy_j;

    // ---- prologue: load tile k=0 (scalar, zero-padded OOB) ----
    {
        const int cx0p = ix0 * PATCH - 20;
        for (int e = tid; e < TILE_E; e += 256) {
            int r = e >> 6;
            int c = e & 63;
            int gx = cx0p + r, gy = cy0 + c;
            float v = 0.f;
            if (gx >= 0 && gx < IMG_H && gy >= 0 && gy < IMG_W)
                v = img[gx * IMG_W + gy];
            winS[e] = v;
        }
    }
    __syncthreads();

    for (int k = 0; k < cnt; k++) {
        const int rx   = (ix0 + k) * PATCH;  // ref patch top row, this step
        const int cx0  = rx - 20;
        const int xoff = max(0, -cx0);
        const int base = 8 * k;              // rqS ring base row

        // ---- prefetch tile k+1 into registers (rows shift by +8) ----
        float pf[10];
        const bool havepf = (k + 1 < cnt);
        if (havepf) {
            const int cx0n = cx0 + PATCH;
#pragma unroll
            for (int s = 0; s < 10; s++) {
                int e = tid + s * 256;
                float v = 0.f;
                if (e < TILE_E) {
                    int r = e >> 6;
                    int c = e & 63;
                    int gx = cx0n + r, gy = cy0 + c;
                    if (gx >= 0 && gx < IMG_H && gy >= 0 && gy < IMG_W)
                        v = img[gx * IMG_W + gy];
                }
                pf[s] = v;
            }
        }

        // ---- Stage B: row sliding sum of squares into the ring ----
        if (k == 0) {
            // full 38 rows -> ring rows 0..37
            for (int e = tid; e < WINDIM * RQ_COLS; e += 256) {
                int r = e / RQ_COLS;
                int c = e - r * RQ_COLS;
                const float* p = &winS[r * WT_COLS + c];
                float s = 0.f;
#pragma unroll
                for (int q = 0; q < PATCH; q++) { float v = p[q]; s += v * v; }
                rqS[e] = s;
            }
        } else {
            // only the 8 new rows (tile rows 30..37 -> ring rows base+30..)
            for (int e = tid; e < 8 * RQ_COLS; e += 256) {
                int rl = e / RQ_COLS;
                int c  = e - rl * RQ_COLS;
                int r  = 30 + rl;
                const float* p = &winS[r * WT_COLS + c];
                float s = 0.f;
#pragma unroll
                for (int q = 0; q < PATCH; q++) { float v = p[q]; s += v * v; }
                rqS[(base + r) * RQ_COLS + c] = s;
            }
        }
        // shifted copy for 8B-aligned odd pairs
        for (int e = tid; e < TILE_E; e += 256) {
            int c = e & 63;
            winS2[e] = (c < 63) ? winS[e + 1] : 0.f;
        }
        __syncthreads();

        // ---- Stage C: vertical sliding sum (8 tall) -> Sc tile ----
        // rows clamped for masked (invalid) u near the top edge -> unused
        for (int e = tid; e < MAXC * SW_COLS; e += 256) {
            int u = e / SW_COLS;
            int c = e - u * SW_COLS;
            int r0 = xoff + u;
            float s = 0.f;
#pragma unroll
            for (int p = 0; p < PATCH; p++) {
                int rr = min(r0 + p, WINDIM - 1);
                s += rqS[(base + rr) * RQ_COLS + c];
            }
            swS[e] = s;
        }
        __syncthreads();

        // ---- Stage D (predicated; NO barriers inside) ----
        if (iy < NR) {
            const int wrowbase = xoff + u0;

            ull bp[4][4];
            ull accp[4][4];
#pragma unroll
            for (int cu = 0; cu < 4; cu++)
#pragma unroll
                for (int v = 0; v < 4; v++) accp[cu][v] = 0ULL;

            // prologue: window pairs for row tt=0
            ull wp[10];
            {
                int rr = min(wrowbase, WINDIM - 1);
                const float* we = &winS [rr * WT_COLS + wcolbase];
                const float* wo = &winS2[rr * WT_COLS + wcolbase];
                ulonglong2 e01 = *reinterpret_cast<const ulonglong2*>(we);
                ulonglong2 o01 = *reinterpret_cast<const ulonglong2*>(wo);
                ulonglong2 e23 = *reinterpret_cast<const ulonglong2*>(we + 4);
                ulonglong2 o23 = *reinterpret_cast<const ulonglong2*>(wo + 4);
                wp[0] = e01.x; wp[1] = o01.x; wp[2] = e01.y; wp[3] = o01.y;
                wp[4] = e23.x; wp[5] = o23.x; wp[6] = e23.y; wp[7] = o23.y;
                wp[8] = *reinterpret_cast<const ull*>(we + 8);
                wp[9] = *reinterpret_cast<const ull*>(wo + 8);
            }

#pragma unroll
            for (int tt = 0; tt < 11; tt++) {
                if (tt < 8) {
                    const ulonglong2* brow = reinterpret_cast<const ulonglong2*>(
                        &winS[(20 + tt) * WT_COLS + bcol]);
                    ulonglong2 b0 = brow[0], b1 = brow[1];
                    bp[tt & 3][0] = b0.x; bp[tt & 3][1] = b0.y;
                    bp[tt & 3][2] = b1.x; bp[tt & 3][3] = b1.y;
                }
                ull wn[10];
                if (tt + 1 < 11) {
                    int rr = min(wrowbase + tt + 1, WINDIM - 1);
                    const float* we = &winS [rr * WT_COLS + wcolbase];
                    const float* wo = &winS2[rr * WT_COLS + wcolbase];
                    ulonglong2 e01 = *reinterpret_cast<const ulonglong2*>(we);
                    ulonglong2 o01 = *reinterpret_cast<const ulonglong2*>(wo);
                    ulonglong2 e23 = *reinterpret_cast<const ulonglong2*>(we + 4);
                    ulonglong2 o23 = *reinterpret_cast<const ulonglong2*>(wo + 4);
                    wn[0] = e01.x; wn[1] = o01.x; wn[2] = e01.y; wn[3] = o01.y;
                    wn[4] = e23.x; wn[5] = o23.x; wn[6] = e23.y; wn[7] = o23.y;
                    wn[8] = *reinterpret_cast<const ull*>(we + 8);
                    wn[9] = *reinterpret_cast<const ull*>(wo + 8);
                }

#pragma unroll
                for (int cu = 3; cu >= 0; cu--) {
                    if (cu <= tt && tt - cu <= 7) {   // p = tt - cu in [0,7]
                        const int p = (tt - cu) & 3;
#pragma unroll
                        for (int qh = 0; qh < 4; qh++) {
                            ffma2(accp[cu][0], bp[p][qh], wp[2 * qh + 0]);
                            ffma2(accp[cu][1], bp[p][qh], wp[2 * qh + 1]);
                            ffma2(accp[cu][2], bp[p][qh], wp[2 * qh + 2]);
                            ffma2(accp[cu][3], bp[p][qh], wp[2 * qh + 3]);
                        }
                    }
                }
                if (tt + 1 < 11) {
#pragma unroll
                    for (int kk = 0; kk < 10; kk++) wp[kk] = wn[kk];
                }
            }

            // ---- epilogue: d2 = Sb + Sc - 2*corr, sqrt, mask, store ----
            const int sx   = max(0, cx0);
            const int cntx = min(IMG_H, rx + 19) - PATCH - sx;
            const float Sb = swS[min(rx, 20) * SW_COLS + (8 * j + 20)];

            float* oref = out + (size_t)((ix0 + k) * NR + iy) * (MAXC * MAXC);
#pragma unroll
            for (int cu = 0; cu < 4; cu++) {
                const int u = u0 + cu;
                if (u < MAXC) {
#pragma unroll
                    for (int cv = 0; cv < 4; cv++) {
                        const int v = v0 + cv;
                        if (v < MAXC) {
                            float r = 0.f;
                            if (u < cntx && v < cnty) {
                                float lo, hi;
                                unpack2(accp[cu][cv], lo, hi);
                                float corr = lo + hi;
                                float Sc = swS[u * SW_COLS + ywoff + v];
                                float d2 = Sb + Sc - 2.f * corr;
                                r = sqrt_approx(fmaxf(d2, 0.f));
                            }
                            store_cs(&oref[u * MAXC + v], r);
                        }
                    }
                }
            }
        }
        __syncthreads();   // all reads of winS/winS2/swS for step k complete

        // ---- commit prefetched tile k+1 to smem ----
        if (havepf) {
#pragma unroll
            for (int s = 0; s < 10; s++) {
                int e = tid + s * 256;
                if (e < TILE_E) winS[e] = pf[s];
            }
        }
        __syncthreads();   // winS now holds tile k+1
    }
}

// ---------------------------------------------------------------------------
extern "C" void kernel_launch(void* const* d_in, const int* in_sizes, int n_in,
                              void* d_out, int out_size) {
    const float* img = (const float*)d_in[0];
    float* out = (float*)d_out;

    dim3 blk(256);
    dim3 g((NR + 3) / 4, (NR + KX - 1) / KX);   // 48 x 24 CTAs
    pm_kernel<<<g, blk>>>(img, out);
}

// round 17
// speedup vs baseline: 1.6488x; 1.1596x over previous
#include <cuda_runtime.h>

// Problem constants (fixed shapes from reference setup_inputs)
#define IMG_H   1536
#define IMG_W   1536
#define NR      191        // reference patches per axis: arange(0, 1528, 8)
#define PATCH   8
#define MAXC    31         // candidates per axis
#define WINDIM  38         // search window span
#define KX      8          // x-tiles marched per CTA

#define WT_COLS 64         // window tile column stride
#define RQ_COLS 56         // row-sq tile columns (used cols <= 54)
#define RQ_ROWS (8 * (KX - 1) + WINDIM)   // 94-row persistent rqS ring
#define SW_ROWS (8 * (KX - 1) + MAXC)     // 87-row persistent swR ring
#define SW_COLS 56
#define TILE_E  (WINDIM * WT_COLS)        // 2432 floats

// dynamic smem carve (float offsets; byte offsets all %16 == 0)
#define OFF_WINS   0
#define OFF_WINS2  TILE_E                     // 2432
#define OFF_RQS    (2 * TILE_E)               // 4864
#define OFF_SWR    (2 * TILE_E + RQ_ROWS * RQ_COLS)   // 10128
#define SMEM_FLOATS (OFF_SWR + SW_ROWS * SW_COLS)     // 15000
#define SMEM_BYTES  (SMEM_FLOATS * 4)                 // 60000

typedef unsigned long long ull;

// ---- packed f32x2 helpers (Blackwell; ptxas never auto-fuses FFMA2) ----
__device__ __forceinline__ void unpack2(ull v, float& lo, float& hi) {
    asm("mov.b64 {%0, %1}, %2;" : "=f"(lo), "=f"(hi) : "l"(v));
}
__device__ __forceinline__ void ffma2(ull& d, ull a, ull b) {
    asm("fma.rn.f32x2 %0, %1, %2, %3;" : "=l"(d) : "l"(a), "l"(b), "l"(d));
}
__device__ __forceinline__ float sqrt_approx(float x) {
    float r;
    asm("sqrt.approx.f32 %0, %1;" : "=f"(r) : "f"(x));
    return r;
}
// streaming store: output is write-once, never re-read -> keep img in L2
__device__ __forceinline__ void store_cs(float* p, float v) {
    asm volatile("st.global.cs.f32 [%0], %1;" :: "l"(p), "f"(v) : "memory");
}

// ---------------------------------------------------------------------------
// Fused kernel, per-CTA x-march of KX=8 tiles. NEW vs R16:
//  - swR (8-row box sums of rqS) is ALSO a persistent ring: step 0 computes
//    rows [xoff,30]; steps k>=1 compute only rows [base+23, base+30]. Valid
//    candidates read exactly ring rows [base+xoff, base+30] (all unclamped
//    sums); masked candidates never read Sc, so no other rows are needed.
//  - winS2 (shifted tile copy) is produced by dual-writes in the prologue /
//    commit loops (winS2[e-1]=v for col(e)>0; col-63 entries zeroed once).
//  - smem is dynamic (60000 B): winS | winS2 | rqS ring | swR ring.
// ---------------------------------------------------------------------------
__global__ void __launch_bounds__(256, 2)
pm_kernel(const float* __restrict__ img, float* __restrict__ out) {
    extern __shared__ __align__(16) float smem[];
    float* winS  = smem + OFF_WINS;
    float* winS2 = smem + OFF_WINS2;
    float* rqS   = smem + OFF_RQS;
    float* swR   = smem + OFF_SWR;

    const int tid = threadIdx.x;
    const int iy0 = blockIdx.x * 4;          // first ref y index of this CTA
    const int ix0 = blockIdx.y * KX;         // first ref x index of this CTA
    const int cnt = min(KX, NR - ix0);       // x-steps this CTA performs
    const int cy0 = iy0 * PATCH - 20;        // window tile origin col (const)

    // ---- y-side constants for Stage D (invariant across the march) ----
    const int j  = tid >> 6;                 // ref slot within CTA (0..3)
    const int t  = tid & 63;
    const int bu = t >> 3, bv = t & 7;
    const int iy = iy0 + j;
    const int ry = iy * PATCH;
    const int ywoff = max(20 - 8 * iy0, 8 * j);
    const int bcol  = 8 * j + 20;            // 16B-aligned
    const int u0 = bu * 4, v0 = bv * 4;
    const int wcolbase = ywoff + v0;         // mult of 4 -> 16B aligned
    const int sy_j = max(0, ry - 20);
    const int cnty = min(IMG_W, ry + 19) - PATCH - sy_j;

    // ---- prologue: load tile k=0 (scalar, zero-padded OOB) + winS2 ----
    {
        const int cx0p = ix0 * PATCH - 20;
        for (int e = tid; e < TILE_E; e += 256) {
            int r = e >> 6;
            int c = e & 63;
            int gx = cx0p + r, gy = cy0 + c;
            float v = 0.f;
            if (gx >= 0 && gx < IMG_H && gy >= 0 && gy < IMG_W)
                v = img[gx * IMG_W + gy];
            winS[e] = v;
            if (c > 0)  winS2[e - 1] = v;    // shifted copy
            if (c == 63) winS2[e] = 0.f;     // col-63: zero once, never touched
        }
    }
    __syncthreads();

    for (int k = 0; k < cnt; k++) {
        const int rx   = (ix0 + k) * PATCH;  // ref patch top row, this step
        const int cx0  = rx - 20;
        const int xoff = max(0, -cx0);
        const int base = 8 * k;              // ring base row

        // ---- prefetch tile k+1 into registers (rows shift by +8) ----
        float pf[10];
        const bool havepf = (k + 1 < cnt);
        if (havepf) {
            const int cx0n = cx0 + PATCH;
#pragma unroll
            for (int s = 0; s < 10; s++) {
                int e = tid + s * 256;
                float v = 0.f;
                if (e < TILE_E) {
                    int r = e >> 6;
                    int c = e & 63;
                    int gx = cx0n + r, gy = cy0 + c;
                    if (gx >= 0 && gx < IMG_H && gy >= 0 && gy < IMG_W)
                        v = img[gx * IMG_W + gy];
                }
                pf[s] = v;
            }
        }

        // ---- Stage B: row sliding sum of squares into the rqS ring ----
        if (k == 0) {
            // full 38 rows -> ring rows 0..37
            for (int e = tid; e < WINDIM * RQ_COLS; e += 256) {
                int r = e / RQ_COLS;
                int c = e - r * RQ_COLS;
                const float* p = &winS[r * WT_COLS + c];
                float s = 0.f;
#pragma unroll
                for (int q = 0; q < PATCH; q++) { float v = p[q]; s += v * v; }
                rqS[e] = s;
            }
        } else {
            // only the 8 new rows (tile rows 30..37 -> ring rows base+30..)
            for (int e = tid; e < 8 * RQ_COLS; e += 256) {
                int rl = e / RQ_COLS;
                int c  = e - rl * RQ_COLS;
                int r  = 30 + rl;
                const float* p = &winS[r * WT_COLS + c];
                float s = 0.f;
#pragma unroll
                for (int q = 0; q < PATCH; q++) { float v = p[q]; s += v * v; }
                rqS[(base + r) * RQ_COLS + c] = s;
            }
        }
        __syncthreads();

        // ---- Stage C: 8-row box sums -> persistent swR ring ----
        // k=0: rows [xoff, 30]; k>=1: rows [base+23, base+30]. All sums
        // unclamped; rows outside this range are never read by valid work.
        if (k == 0) {
            const int n0 = (MAXC - xoff) * SW_COLS;
            for (int e = tid; e < n0; e += 256) {
                int rl = e / SW_COLS;
                int c  = e - rl * SW_COLS;
                int rr = xoff + rl;
                float s = 0.f;
#pragma unroll
                for (int p = 0; p < PATCH; p++)
                    s += rqS[(rr + p) * RQ_COLS + c];
                swR[rr * SW_COLS + c] = s;
            }
        } else {
            for (int e = tid; e < 8 * SW_COLS; e += 256) {
                int rl = e / SW_COLS;
                int c  = e - rl * SW_COLS;
                int rr = base + 23 + rl;
                float s = 0.f;
#pragma unroll
                for (int p = 0; p < PATCH; p++)
                    s += rqS[(rr + p) * RQ_COLS + c];
                swR[rr * SW_COLS + c] = s;
            }
        }
        __syncthreads();

        // ---- Stage D (predicated; NO barriers inside) ----
        if (iy < NR) {
            const int wrowbase = xoff + u0;

            ull bp[4][4];
            ull accp[4][4];
#pragma unroll
            for (int cu = 0; cu < 4; cu++)
#pragma unroll
                for (int v = 0; v < 4; v++) accp[cu][v] = 0ULL;

            // prologue: window pairs for row tt=0
            ull wp[10];
            {
                int rr = min(wrowbase, WINDIM - 1);
                const float* we = &winS [rr * WT_COLS + wcolbase];
                const float* wo = &winS2[rr * WT_COLS + wcolbase];
                ulonglong2 e01 = *reinterpret_cast<const ulonglong2*>(we);
                ulonglong2 o01 = *reinterpret_cast<const ulonglong2*>(wo);
                ulonglong2 e23 = *reinterpret_cast<const ulonglong2*>(we + 4);
                ulonglong2 o23 = *reinterpret_cast<const ulonglong2*>(wo + 4);
                wp[0] = e01.x; wp[1] = o01.x; wp[2] = e01.y; wp[3] = o01.y;
                wp[4] = e23.x; wp[5] = o23.x; wp[6] = e23.y; wp[7] = o23.y;
                wp[8] = *reinterpret_cast<const ull*>(we + 8);
                wp[9] = *reinterpret_cast<const ull*>(wo + 8);
            }

#pragma unroll
            for (int tt = 0; tt < 11; tt++) {
                if (tt < 8) {
                    const ulonglong2* brow = reinterpret_cast<const ulonglong2*>(
                        &winS[(20 + tt) * WT_COLS + bcol]);
                    ulonglong2 b0 = brow[0], b1 = brow[1];
                    bp[tt & 3][0] = b0.x; bp[tt & 3][1] = b0.y;
                    bp[tt & 3][2] = b1.x; bp[tt & 3][3] = b1.y;
                }
                ull wn[10];
                if (tt + 1 < 11) {
                    int rr = min(wrowbase + tt + 1, WINDIM - 1);
                    const float* we = &winS [rr * WT_COLS + wcolbase];
                    const float* wo = &winS2[rr * WT_COLS + wcolbase];
                    ulonglong2 e01 = *reinterpret_cast<const ulonglong2*>(we);
                    ulonglong2 o01 = *reinterpret_cast<const ulonglong2*>(wo);
                    ulonglong2 e23 = *reinterpret_cast<const ulonglong2*>(we + 4);
                    ulonglong2 o23 = *reinterpret_cast<const ulonglong2*>(wo + 4);
                    wn[0] = e01.x; wn[1] = o01.x; wn[2] = e01.y; wn[3] = o01.y;
                    wn[4] = e23.x; wn[5] = o23.x; wn[6] = e23.y; wn[7] = o23.y;
                    wn[8] = *reinterpret_cast<const ull*>(we + 8);
                    wn[9] = *reinterpret_cast<const ull*>(wo + 8);
                }

#pragma unroll
                for (int cu = 3; cu >= 0; cu--) {
                    if (cu <= tt && tt - cu <= 7) {   // p = tt - cu in [0,7]
                        const int p = (tt - cu) & 3;
#pragma unroll
                        for (int qh = 0; qh < 4; qh++) {
                            ffma2(accp[cu][0], bp[p][qh], wp[2 * qh + 0]);
                            ffma2(accp[cu][1], bp[p][qh], wp[2 * qh + 1]);
                            ffma2(accp[cu][2], bp[p][qh], wp[2 * qh + 2]);
                            ffma2(accp[cu][3], bp[p][qh], wp[2 * qh + 3]);
                        }
                    }
                }
                if (tt + 1 < 11) {
#pragma unroll
                    for (int kk = 0; kk < 10; kk++) wp[kk] = wn[kk];
                }
            }

            // ---- epilogue: d2 = Sb + Sc - 2*corr, sqrt, mask, store ----
            const int sx   = max(0, cx0);
            const int cntx = min(IMG_H, rx + 19) - PATCH - sx;
            const int srow = base + xoff;    // swR ring row of candidate u=0
            const float Sb = swR[(base + 20) * SW_COLS + (8 * j + 20)];

            float* oref = out + (size_t)((ix0 + k) * NR + iy) * (MAXC * MAXC);
#pragma unroll
            for (int cu = 0; cu < 4; cu++) {
                const int u = u0 + cu;
                if (u < MAXC) {
#pragma unroll
                    for (int cv = 0; cv < 4; cv++) {
                        const int v = v0 + cv;
                        if (v < MAXC) {
                            float r = 0.f;
                            if (u < cntx && v < cnty) {
                                float lo, hi;
                                unpack2(accp[cu][cv], lo, hi);
                                float corr = lo + hi;
                                float Sc = swR[(srow + u) * SW_COLS + ywoff + v];
                                float d2 = Sb + Sc - 2.f * corr;
                                r = sqrt_approx(fmaxf(d2, 0.f));
                            }
                            store_cs(&oref[u * MAXC + v], r);
                        }
                    }
                }
            }
        }
        __syncthreads();   // all reads of winS/winS2/swR for step k complete

        // ---- commit prefetched tile k+1 to smem (winS + shifted winS2) ----
        if (havepf) {
#pragma unroll
            for (int s = 0; s < 10; s++) {
                int e = tid + s * 256;
                if (e < TILE_E) {
                    float v = pf[s];
                    winS[e] = v;
                    if ((e & 63) > 0) winS2[e - 1] = v;
                }
            }
        }
        __syncthreads();   // winS/winS2 now hold tile k+1
    }
}

// ---------------------------------------------------------------------------
extern "C" void kernel_launch(void* const* d_in, const int* in_sizes, int n_in,
                              void* d_out, int out_size) {
    const float* img = (const float*)d_in[0];
    float* out = (float*)d_out;

    cudaFuncSetAttribute(pm_kernel,
                         cudaFuncAttributeMaxDynamicSharedMemorySize,
                         SMEM_BYTES);

    dim3 blk(256);
    dim3 g((NR + 3) / 4, (NR + KX - 1) / KX);   // 48 x 24 CTAs
    pm_kernel<<<g, blk, SMEM_BYTES>>>(img, out);
}